// round 1
// baseline (speedup 1.0000x reference)
#include <cuda_runtime.h>

// Problem constants
#define KS    5
#define NTAP  25
#define OH    508
#define OW    508
#define IH    512
#define IW    512
#define CI    3
#define BATCH 8

// weighted total elements = 8*3*508*508
#define WTOT  6193536

// Tile config
#define TW4   32              // float4 columns per tile (x)
#define TWPX  (TW4 * 4)       // 128 pixels wide
#define TH    8               // rows per tile
#define SW    (TWPX + 4)      // 132 floats per smem row (multiple of 4 -> float4 ok)
#define SROWS (TH + 4)        // 12 rows

__global__ __launch_bounds__(TW4 * TH, 3)
void apply_kernels_k(const float* __restrict__ kern,   // [8][25][508][508]
                     const float* __restrict__ tens,   // [8][3][512][512]
                     float* __restrict__ out)          // weighted ++ kernel_sum
{
    __shared__ float s_t[CI][SROWS][SW];

    const int b  = blockIdx.z;
    const int i0 = blockIdx.y * TH;
    const int j0 = blockIdx.x * TWPX;

    // ---- cooperative tensor tile load (3 ch, 12 rows, 132 cols) as float4 ----
    {
        const int tid = threadIdx.y * TW4 + threadIdx.x;
        const int NV4 = CI * SROWS * (SW / 4);   // 3*12*33 = 1188 float4 slots
        #pragma unroll 1
        for (int idx = tid; idx < NV4; idx += TW4 * TH) {
            const int c    = idx / (SROWS * (SW / 4));
            const int rem  = idx % (SROWS * (SW / 4));
            const int r    = rem / (SW / 4);
            const int q4   = rem % (SW / 4);
            const int grow = i0 + r;
            const int gcol = j0 + q4 * 4;
            float4 v = make_float4(0.f, 0.f, 0.f, 0.f);
            if (grow < IH && gcol < IW) {
                v = *reinterpret_cast<const float4*>(
                        &tens[(((size_t)b * CI + c) * IH + grow) * IW + gcol]);
            }
            *reinterpret_cast<float4*>(&s_t[c][r][q4 * 4]) = v;
        }
    }
    __syncthreads();

    const int tx = threadIdx.x;
    const int ty = threadIdx.y;
    const int i  = i0 + ty;
    const int j  = j0 + tx * 4;
    if (i >= OH || j >= OW) return;

    float acc0[4] = {0.f, 0.f, 0.f, 0.f};
    float acc1[4] = {0.f, 0.f, 0.f, 0.f};
    float acc2[4] = {0.f, 0.f, 0.f, 0.f};
    float ssum[4] = {0.f, 0.f, 0.f, 0.f};

    const size_t kbase = ((size_t)b * NTAP) * OH * OW + (size_t)i * OW + j;

    #pragma unroll
    for (int di = 0; di < KS; ++di) {
        // register-cache the 8 tensor values needed per channel for this row
        float r0[8], r1[8], r2[8];
        {
            const int sc = tx * 4;
            float4 a, bb;
            a  = *reinterpret_cast<const float4*>(&s_t[0][ty + di][sc]);
            bb = *reinterpret_cast<const float4*>(&s_t[0][ty + di][sc + 4]);
            r0[0]=a.x; r0[1]=a.y; r0[2]=a.z; r0[3]=a.w;
            r0[4]=bb.x; r0[5]=bb.y; r0[6]=bb.z; r0[7]=bb.w;
            a  = *reinterpret_cast<const float4*>(&s_t[1][ty + di][sc]);
            bb = *reinterpret_cast<const float4*>(&s_t[1][ty + di][sc + 4]);
            r1[0]=a.x; r1[1]=a.y; r1[2]=a.z; r1[3]=a.w;
            r1[4]=bb.x; r1[5]=bb.y; r1[6]=bb.z; r1[7]=bb.w;
            a  = *reinterpret_cast<const float4*>(&s_t[2][ty + di][sc]);
            bb = *reinterpret_cast<const float4*>(&s_t[2][ty + di][sc + 4]);
            r2[0]=a.x; r2[1]=a.y; r2[2]=a.z; r2[3]=a.w;
            r2[4]=bb.x; r2[5]=bb.y; r2[6]=bb.z; r2[7]=bb.w;
        }
        #pragma unroll
        for (int dj = 0; dj < KS; ++dj) {
            const int tap = di * KS + dj;
            const float4 k4 = __ldg(reinterpret_cast<const float4*>(
                &kern[kbase + (size_t)tap * (OH * OW)]));
            const float kv[4] = {k4.x, k4.y, k4.z, k4.w};
            #pragma unroll
            for (int l = 0; l < 4; ++l) {
                const float s = kv[l];
                ssum[l] += s;
                acc0[l] = fmaf(s, r0[l + dj], acc0[l]);
                acc1[l] = fmaf(s, r1[l + dj], acc1[l]);
                acc2[l] = fmaf(s, r2[l + dj], acc2[l]);
            }
        }
    }

    // ---- stores: weighted (3 channels) then kernel_sum ----
    const size_t pix = (size_t)i * OW + j;
    *reinterpret_cast<float4*>(&out[(((size_t)b * CI + 0) * OH * OW) + pix]) =
        make_float4(acc0[0], acc0[1], acc0[2], acc0[3]);
    *reinterpret_cast<float4*>(&out[(((size_t)b * CI + 1) * OH * OW) + pix]) =
        make_float4(acc1[0], acc1[1], acc1[2], acc1[3]);
    *reinterpret_cast<float4*>(&out[(((size_t)b * CI + 2) * OH * OW) + pix]) =
        make_float4(acc2[0], acc2[1], acc2[2], acc2[3]);
    *reinterpret_cast<float4*>(&out[WTOT + (size_t)b * OH * OW + pix]) =
        make_float4(ssum[0], ssum[1], ssum[2], ssum[3]);
}

extern "C" void kernel_launch(void* const* d_in, const int* in_sizes, int n_in,
                              void* d_out, int out_size)
{
    const float* kern = (const float*)d_in[0];   // (8, 25, 508, 508)
    const float* tens = (const float*)d_in[1];   // (8, 3, 512, 512)
    float* out = (float*)d_out;

    dim3 block(TW4, TH, 1);                       // 256 threads
    dim3 grid((OW / 4 + TW4 - 1) / TW4,           // 127/32 -> 4
              (OH + TH - 1) / TH,                 // 64
              BATCH);                             // 8
    apply_kernels_k<<<grid, block>>>(kern, tens, out);
}

// round 2
// speedup vs baseline: 1.1317x; 1.1317x over previous
#include <cuda_runtime.h>

// Problem constants
#define KS    5
#define NTAP  25
#define OH    508
#define OW    508
#define IH    512
#define IW    512
#define CI    3
#define BATCH 8

#define PLANE (OH * OW)          // 258064 floats, %4 == 0
#define PLANE4 (PLANE / 4)       // 64516 float4s
// weighted total elements = 8*3*508*508
#define WTOT  6193536

// Tile config
#define TW4   32              // float4 columns per tile (x)
#define TWPX  (TW4 * 4)       // 128 pixels wide
#define TH    8               // rows per tile
#define SW    (TWPX + 4)      // 132 floats per smem row
#define SROWS (TH + 4)        // 12 rows

__global__ __launch_bounds__(TW4 * TH, 3)
void apply_kernels_k(const float* __restrict__ kern,   // [8][25][508][508]
                     const float* __restrict__ tens,   // [8][3][512][512]
                     float* __restrict__ out)          // weighted ++ kernel_sum
{
    __shared__ float s_t[CI][SROWS][SW];

    const int b  = blockIdx.z;
    const int i0 = blockIdx.y * TH;
    const int j0 = blockIdx.x * TWPX;

    const int tx = threadIdx.x;
    const int ty = threadIdx.y;
    // clamp instead of early-return: out-of-range threads duplicate valid work
    const int i  = min(i0 + ty, OH - 1);
    const int j  = min(j0 + tx * 4, OW - 4);

    // Base pointer for this thread's tap stream (16B aligned: j%4==0, PLANE%4==0)
    const float4* kp = reinterpret_cast<const float4*>(
        kern + ((size_t)b * NTAP) * PLANE + (size_t)i * OW + j);

    // ---- kick off first two tap loads BEFORE the smem tile fill/sync so the
    //      DRAM pipe is busy during the barrier ----
    float4 kb0 = __ldcs(kp);
    float4 kb1 = __ldcs(kp + PLANE4);

    // ---- cooperative tensor tile load (3 ch, 12 rows, 132 cols) as float4 ----
    {
        const int tid = ty * TW4 + tx;
        const int NV4 = CI * SROWS * (SW / 4);   // 3*12*33 = 1188 float4 slots
        #pragma unroll 1
        for (int idx = tid; idx < NV4; idx += TW4 * TH) {
            const int c    = idx / (SROWS * (SW / 4));
            const int rem  = idx % (SROWS * (SW / 4));
            const int r    = rem / (SW / 4);
            const int q4   = rem % (SW / 4);
            const int grow = i0 + r;
            const int gcol = j0 + q4 * 4;
            float4 v = make_float4(0.f, 0.f, 0.f, 0.f);
            if (grow < IH && gcol < IW) {
                v = *reinterpret_cast<const float4*>(
                        &tens[(((size_t)b * CI + c) * IH + grow) * IW + gcol]);
            }
            *reinterpret_cast<float4*>(&s_t[c][r][q4 * 4]) = v;
        }
    }
    __syncthreads();

    const int li = i - i0;           // local row (after clamp)
    const int lj = (j - j0);         // local col in floats

    float acc0[4] = {0.f, 0.f, 0.f, 0.f};
    float acc1[4] = {0.f, 0.f, 0.f, 0.f};
    float acc2[4] = {0.f, 0.f, 0.f, 0.f};
    float ssum[4] = {0.f, 0.f, 0.f, 0.f};

    float r0[8], r1[8], r2[8];

    #pragma unroll
    for (int tap = 0; tap < NTAP; ++tap) {
        const int di = tap / KS;
        const int dj = tap % KS;

        // consume from the 2-deep ring, refill 2 ahead
        float4 k4;
        if ((tap & 1) == 0) { k4 = kb0; if (tap + 2 < NTAP) kb0 = __ldcs(kp + (tap + 2) * PLANE4); }
        else                { k4 = kb1; if (tap + 2 < NTAP) kb1 = __ldcs(kp + (tap + 2) * PLANE4); }

        // refresh the per-row register cache at the start of each kernel row
        if (dj == 0) {
            float4 a, bb;
            a  = *reinterpret_cast<const float4*>(&s_t[0][li + di][lj]);
            bb = *reinterpret_cast<const float4*>(&s_t[0][li + di][lj + 4]);
            r0[0]=a.x; r0[1]=a.y; r0[2]=a.z; r0[3]=a.w;
            r0[4]=bb.x; r0[5]=bb.y; r0[6]=bb.z; r0[7]=bb.w;
            a  = *reinterpret_cast<const float4*>(&s_t[1][li + di][lj]);
            bb = *reinterpret_cast<const float4*>(&s_t[1][li + di][lj + 4]);
            r1[0]=a.x; r1[1]=a.y; r1[2]=a.z; r1[3]=a.w;
            r1[4]=bb.x; r1[5]=bb.y; r1[6]=bb.z; r1[7]=bb.w;
            a  = *reinterpret_cast<const float4*>(&s_t[2][li + di][lj]);
            bb = *reinterpret_cast<const float4*>(&s_t[2][li + di][lj + 4]);
            r2[0]=a.x; r2[1]=a.y; r2[2]=a.z; r2[3]=a.w;
            r2[4]=bb.x; r2[5]=bb.y; r2[6]=bb.z; r2[7]=bb.w;
        }

        const float kv[4] = {k4.x, k4.y, k4.z, k4.w};
        #pragma unroll
        for (int l = 0; l < 4; ++l) {
            const float s = kv[l];
            ssum[l] += s;
            acc0[l] = fmaf(s, r0[l + dj], acc0[l]);
            acc1[l] = fmaf(s, r1[l + dj], acc1[l]);
            acc2[l] = fmaf(s, r2[l + dj], acc2[l]);
        }
    }

    // ---- stores: weighted (3 channels) then kernel_sum ----
    const size_t pix = (size_t)i * OW + j;
    *reinterpret_cast<float4*>(&out[(((size_t)b * CI + 0) * (size_t)PLANE) + pix]) =
        make_float4(acc0[0], acc0[1], acc0[2], acc0[3]);
    *reinterpret_cast<float4*>(&out[(((size_t)b * CI + 1) * (size_t)PLANE) + pix]) =
        make_float4(acc1[0], acc1[1], acc1[2], acc1[3]);
    *reinterpret_cast<float4*>(&out[(((size_t)b * CI + 2) * (size_t)PLANE) + pix]) =
        make_float4(acc2[0], acc2[1], acc2[2], acc2[3]);
    *reinterpret_cast<float4*>(&out[WTOT + (size_t)b * (size_t)PLANE + pix]) =
        make_float4(ssum[0], ssum[1], ssum[2], ssum[3]);
}

extern "C" void kernel_launch(void* const* d_in, const int* in_sizes, int n_in,
                              void* d_out, int out_size)
{
    const float* kern = (const float*)d_in[0];   // (8, 25, 508, 508)
    const float* tens = (const float*)d_in[1];   // (8, 3, 512, 512)
    float* out = (float*)d_out;

    dim3 block(TW4, TH, 1);                       // 256 threads
    dim3 grid((OW / 4 + TW4 - 1) / TW4,           // 4
              (OH + TH - 1) / TH,                 // 64
              BATCH);                             // 8
    apply_kernels_k<<<grid, block>>>(kern, tens, out);
}

// round 3
// speedup vs baseline: 1.1884x; 1.0500x over previous
#include <cuda_runtime.h>

// Problem constants
#define KS    5
#define NTAP  25
#define OH    508
#define OW    508
#define IH    512
#define IW    512
#define CI    3
#define BATCH 8

#define PLANE (OH * OW)          // 258064 floats, %4 == 0
#define PLANE4 (PLANE / 4)       // 64516 float4s
#define WTOT  6193536            // 8*3*508*508

// Tile config
#define TW4   32              // float4 columns per tile (x)
#define TWPX  (TW4 * 4)       // 128 pixels wide
#define TH    8               // rows per tile
#define SW    (TWPX + 4)      // 132 floats per smem row
#define SROWS (TH + 4)        // 12 rows

__global__ __launch_bounds__(TW4 * TH, 2)
void apply_kernels_k(const float* __restrict__ kern,   // [8][25][508][508]
                     const float* __restrict__ tens,   // [8][3][512][512]
                     float* __restrict__ out)          // weighted ++ kernel_sum
{
    __shared__ float s_t[CI][SROWS][SW];

    const int b  = blockIdx.z;
    const int i0 = blockIdx.y * TH;
    const int j0 = blockIdx.x * TWPX;

    const int tx = threadIdx.x;
    const int ty = threadIdx.y;
    // clamp instead of early-return: out-of-range threads duplicate valid work
    const int i  = min(i0 + ty, OH - 1);
    const int j  = min(j0 + tx * 4, OW - 4);

    // Base pointer for this thread's tap stream (16B aligned)
    const float4* kp = reinterpret_cast<const float4*>(
        kern + ((size_t)b * NTAP) * PLANE + (size_t)i * OW + j);

    // ---- issue the FIRST FULL TAP ROW (5 independent LDG.128) before the
    //      smem tile fill + barrier: DRAM pipe busy during the sync ----
    float4 kr[KS];
    #pragma unroll
    for (int t = 0; t < KS; ++t) kr[t] = __ldcs(kp + t * PLANE4);

    // ---- cooperative tensor tile load (3 ch, 12 rows, 132 cols) as float4 ----
    {
        const int tid = ty * TW4 + tx;
        const int NV4 = CI * SROWS * (SW / 4);   // 1188 float4 slots
        #pragma unroll 1
        for (int idx = tid; idx < NV4; idx += TW4 * TH) {
            const int c    = idx / (SROWS * (SW / 4));
            const int rem  = idx % (SROWS * (SW / 4));
            const int r    = rem / (SW / 4);
            const int q4   = rem % (SW / 4);
            const int grow = i0 + r;
            const int gcol = j0 + q4 * 4;
            float4 v = make_float4(0.f, 0.f, 0.f, 0.f);
            if (grow < IH && gcol < IW) {
                v = *reinterpret_cast<const float4*>(
                        &tens[(((size_t)b * CI + c) * IH + grow) * IW + gcol]);
            }
            *reinterpret_cast<float4*>(&s_t[c][r][q4 * 4]) = v;
        }
    }
    __syncthreads();

    const int li = i - i0;           // local row (after clamp)
    const int lj = (j - j0);         // local col in floats

    float acc0[4] = {0.f, 0.f, 0.f, 0.f};
    float acc1[4] = {0.f, 0.f, 0.f, 0.f};
    float acc2[4] = {0.f, 0.f, 0.f, 0.f};
    float ssum[4] = {0.f, 0.f, 0.f, 0.f};

    #pragma unroll
    for (int di = 0; di < KS; ++di) {
        // ---- issue next tap row (5 independent LDGs, front-batched) ----
        float4 kn[KS];
        if (di < KS - 1) {
            #pragma unroll
            for (int t = 0; t < KS; ++t)
                kn[t] = __ldcs(kp + ((di + 1) * KS + t) * PLANE4);
        }

        // ---- register-cache the 8 tensor floats per channel for this row ----
        float r0[8], r1[8], r2[8];
        {
            float4 a, bb;
            a  = *reinterpret_cast<const float4*>(&s_t[0][li + di][lj]);
            bb = *reinterpret_cast<const float4*>(&s_t[0][li + di][lj + 4]);
            r0[0]=a.x; r0[1]=a.y; r0[2]=a.z; r0[3]=a.w;
            r0[4]=bb.x; r0[5]=bb.y; r0[6]=bb.z; r0[7]=bb.w;
            a  = *reinterpret_cast<const float4*>(&s_t[1][li + di][lj]);
            bb = *reinterpret_cast<const float4*>(&s_t[1][li + di][lj + 4]);
            r1[0]=a.x; r1[1]=a.y; r1[2]=a.z; r1[3]=a.w;
            r1[4]=bb.x; r1[5]=bb.y; r1[6]=bb.z; r1[7]=bb.w;
            a  = *reinterpret_cast<const float4*>(&s_t[2][li + di][lj]);
            bb = *reinterpret_cast<const float4*>(&s_t[2][li + di][lj + 4]);
            r2[0]=a.x; r2[1]=a.y; r2[2]=a.z; r2[3]=a.w;
            r2[4]=bb.x; r2[5]=bb.y; r2[6]=bb.z; r2[7]=bb.w;
        }

        // ---- consume current tap row (loads for next row in flight) ----
        #pragma unroll
        for (int dj = 0; dj < KS; ++dj) {
            const float4 k4 = kr[dj];
            const float kv[4] = {k4.x, k4.y, k4.z, k4.w};
            #pragma unroll
            for (int l = 0; l < 4; ++l) {
                const float s = kv[l];
                ssum[l] += s;
                acc0[l] = fmaf(s, r0[l + dj], acc0[l]);
                acc1[l] = fmaf(s, r1[l + dj], acc1[l]);
                acc2[l] = fmaf(s, r2[l + dj], acc2[l]);
            }
        }

        if (di < KS - 1) {
            #pragma unroll
            for (int t = 0; t < KS; ++t) kr[t] = kn[t];
        }
    }

    // ---- stores: weighted (3 channels) then kernel_sum ----
    const size_t pix = (size_t)i * OW + j;
    *reinterpret_cast<float4*>(&out[(((size_t)b * CI + 0) * (size_t)PLANE) + pix]) =
        make_float4(acc0[0], acc0[1], acc0[2], acc0[3]);
    *reinterpret_cast<float4*>(&out[(((size_t)b * CI + 1) * (size_t)PLANE) + pix]) =
        make_float4(acc1[0], acc1[1], acc1[2], acc1[3]);
    *reinterpret_cast<float4*>(&out[(((size_t)b * CI + 2) * (size_t)PLANE) + pix]) =
        make_float4(acc2[0], acc2[1], acc2[2], acc2[3]);
    *reinterpret_cast<float4*>(&out[WTOT + (size_t)b * (size_t)PLANE + pix]) =
        make_float4(ssum[0], ssum[1], ssum[2], ssum[3]);
}

extern "C" void kernel_launch(void* const* d_in, const int* in_sizes, int n_in,
                              void* d_out, int out_size)
{
    const float* kern = (const float*)d_in[0];   // (8, 25, 508, 508)
    const float* tens = (const float*)d_in[1];   // (8, 3, 512, 512)
    float* out = (float*)d_out;

    dim3 block(TW4, TH, 1);                       // 256 threads
    dim3 grid((OW / 4 + TW4 - 1) / TW4,           // 4
              (OH + TH - 1) / TH,                 // 64
              BATCH);                             // 8
    apply_kernels_k<<<grid, block>>>(kern, tens, out);
}